// round 15
// baseline (speedup 1.0000x reference)
#include <cuda_runtime.h>
#include <cuda_bf16.h>
#include <cuda_fp16.h>
#include <math.h>

#define BATCH 8
#define DIM 96
#define HH 192
#define WW 192
#define NEXP 6
#define TOPK 3

#define TR 16             // output rows per tile
#define NIN (TR + 4)      // input rows per tile (20)
#define NC1 (TR + 2)      // conv1 rows per tile (18)

typedef unsigned long long u64;

// ---------- packed f32x2 helpers (sm_103a) ----------
__device__ __forceinline__ u64 pk2(float lo, float hi) {
    u64 d; asm("mov.b64 %0, {%1, %2};" : "=l"(d) : "f"(lo), "f"(hi)); return d;
}
__device__ __forceinline__ void upk2(u64 d, float& lo, float& hi) {
    asm("mov.b64 {%0, %1}, %2;" : "=f"(lo), "=f"(hi) : "l"(d));
}
__device__ __forceinline__ u64 fma2(u64 a, u64 b, u64 c) {
    u64 d; asm("fma.rn.f32x2 %0, %1, %2, %3;" : "=l"(d) : "l"(a), "l"(b), "l"(c)); return d;
}
__device__ __forceinline__ u64 add2(u64 a, u64 b) {
    u64 d; asm("add.rn.f32x2 %0, %1, %2;" : "=l"(d) : "l"(a), "l"(b)); return d;
}

// ---------- device scratch ----------
__device__ float g_pooled[BATCH * DIM];
__device__ int   g_idx[BATCH * TOPK];
__device__ float g_w[BATCH * TOPK];
__device__ unsigned int g_done = 0;   // self-resetting completion counter

// ---------------------------------------------------------------
// Kernel A: fused pooling + gate (last-block pattern, self-resetting).
// ---------------------------------------------------------------
__global__ __launch_bounds__(256) void pool_gate_kernel(
    const float* __restrict__ x,
    const float* __restrict__ w_fc0, const float* __restrict__ b_fc0,
    const float* __restrict__ w_fc1, const float* __restrict__ b_fc1)
{
    __shared__ float smx[8], ssm[8];
    __shared__ int   s_last;
    __shared__ float sh_g[BATCH][NEXP], sh_nz[BATCH][NEXP];

    const int bc = blockIdx.x;
    const int tid = threadIdx.x;
    const float4* p4 = reinterpret_cast<const float4*>(x + (size_t)bc * (HH * WW));
    float mx = -1e30f, sm = 0.f;
    for (int i = tid; i < (HH * WW / 4); i += 256) {
        float4 v = p4[i];
        mx = fmaxf(mx, fmaxf(fmaxf(v.x, v.y), fmaxf(v.z, v.w)));
        sm += (v.x + v.y) + (v.z + v.w);
    }
#pragma unroll
    for (int o = 16; o; o >>= 1) {
        mx = fmaxf(mx, __shfl_xor_sync(0xffffffffu, mx, o));
        sm += __shfl_xor_sync(0xffffffffu, sm, o);
    }
    int w = tid >> 5, l = tid & 31;
    if (l == 0) { smx[w] = mx; ssm[w] = sm; }
    __syncthreads();
    if (tid == 0) {
        float M = smx[0], S = ssm[0];
#pragma unroll
        for (int i = 1; i < 8; i++) { M = fmaxf(M, smx[i]); S += ssm[i]; }
        g_pooled[bc] = M + S * (1.0f / (HH * WW));
        __threadfence();                                   // release g_pooled
        unsigned int old = atomicAdd(&g_done, 1u);
        s_last = (old == (unsigned)(BATCH * DIM - 1)) ? 1 : 0;
    }
    __syncthreads();
    if (!s_last) return;

    // ---- last block: gate ----
    __threadfence();                                       // acquire g_pooled
    if (tid == 0) g_done = 0;                              // reset for replay
    if (tid < BATCH * NEXP) {
        int b = tid / NEXP, e = tid - b * NEXP;
        const float* p = g_pooled + b * DIM;
        float d0 = b_fc0[e], d1 = b_fc1[e];
        for (int c = 0; c < DIM; c++) {
            float pv = p[c];
            d0 = fmaf(pv, w_fc0[e * DIM + c], d0);
            d1 = fmaf(pv, w_fc1[e * DIM + c], d1);
        }
        sh_g[b][e]  = (d1 >= 0.f) ? d1 : 0.2f * d1;                  // leaky_relu 0.2
        sh_nz[b][e] = fmaxf(d0, 0.f) + log1pf(expf(-fabsf(d0)));     // stable softplus
    }
    __syncthreads();
    if (tid < BATCH) {
        int b = tid;
        float g[NEXP], nz[NEXP];
#pragma unroll
        for (int e = 0; e < NEXP; e++) { g[e] = sh_g[b][e]; nz[e] = sh_nz[b][e]; }
        float mu = 0.f;
#pragma unroll
        for (int e = 0; e < NEXP; e++) mu += nz[e];
        mu *= (1.0f / NEXP);
        float var = 0.f;
#pragma unroll
        for (int e = 0; e < NEXP; e++) { float d = nz[e] - mu; var += d * d; }
        float sd = sqrtf(var / (NEXP - 1));                          // ddof=1
        float sc[NEXP];
#pragma unroll
        for (int e = 0; e < NEXP; e++) sc[e] = g[e] + (nz[e] - mu) / sd;

        bool used[NEXP] = {false, false, false, false, false, false};
        int idx[TOPK];
#pragma unroll
        for (int k = 0; k < TOPK; k++) {
            float best = -1e30f; int bi = 0;
#pragma unroll
            for (int e = 0; e < NEXP; e++)
                if (!used[e] && sc[e] > best) { best = sc[e]; bi = e; }
            used[bi] = true;
            idx[k] = bi;
        }
        float m = fmaxf(g[idx[0]], fmaxf(g[idx[1]], g[idx[2]]));
        float ex[TOPK], s = 0.f;
#pragma unroll
        for (int k = 0; k < TOPK; k++) { ex[k] = expf(g[idx[k]] - m); s += ex[k]; }
        float inv = 1.0f / s;
#pragma unroll
        for (int k = 0; k < TOPK; k++) {
            g_idx[b * TOPK + k] = idx[k];
            g_w[b * TOPK + k]   = ex[k] * inv;
        }
    }
}

// ---------------------------------------------------------------
// Kernel C: fused conv1 -> relu -> conv2 -> weighted sum (f32x2).
// Scatter form, 16-row tiles, fp16x2 c1, prefetched LDS, biases
// hoisted into acc init. EDGE template for the 2 boundary row-tiles.
// ---------------------------------------------------------------
#define INW 196
#define INW2 98
#define C1PW 100   // u32 pairs per c1 row

struct P3 { u64 p0, p1, p2; };

__device__ __forceinline__ P3 load3(const float2* row, int t) {
    float2 L = row[t];       // cols (2t-1, 2t)
    float2 R = row[t + 1];   // cols (2t+1, 2t+2)
    P3 r;
    r.p0 = pk2(L.x, L.y);
    r.p1 = pk2(L.y, R.x);
    r.p2 = pk2(R.x, R.y);
    return r;
}

template <bool EDGE>
__device__ __forceinline__ void run_experts(
    const float2* in2, __half2* c1h, u64* acc, int t, int h0, int b, int c,
    const float* __restrict__ ew1, const float* __restrict__ eb1,
    const float* __restrict__ ew2, const float* __restrict__ eb2)
{
    for (int ki = 0; ki < TOPK; ki++) {
        const int   e   = g_idx[b * TOPK + ki];
        const float cof = g_w[b * TOPK + ki];
        const float* w1 = ew1 + ((size_t)e * DIM + c) * 9;
        const float* w2 = ew2 + ((size_t)e * DIM + c) * 9;

        // ---- conv1 + relu -> c1h (scatter, 3-slot circular acc, prefetch) ----
        {
            const u64 K0 = pk2(w1[0], w1[0]), K1 = pk2(w1[1], w1[1]), K2 = pk2(w1[2], w1[2]);
            const u64 K3 = pk2(w1[3], w1[3]), K4 = pk2(w1[4], w1[4]), K5 = pk2(w1[5], w1[5]);
            const u64 K6 = pk2(w1[6], w1[6]), K7 = pk2(w1[7], w1[7]), K8 = pk2(w1[8], w1[8]);
            const float b1v = eb1[e * DIM + c];
            const u64 B1 = pk2(b1v, b1v);

            u64 s[3];
            P3 X = load3(in2, t);               // prefetch row 0
#pragma unroll
            for (int ri = 0; ri < NIN; ri++) {
                P3 Xn;
                if (ri + 1 < NIN) Xn = load3(in2 + (ri + 1) * INW2, t);
                if (ri >= 2) {          // finish c1 row (ri-2), store as fp16x2
                    u64 v = fma2(K6, X.p0, fma2(K7, X.p1, fma2(K8, X.p2, s[(ri - 2) % 3])));
                    float v0, v1; upk2(v, v0, v1);
                    float r0 = fmaxf(v0, 0.f), r1 = fmaxf(v1, 0.f);
                    if (EDGE) {
                        const int hr = h0 + (ri - 2) - 1;
                        const bool hok = (unsigned)hr < (unsigned)HH;
                        // conv2's zero padding lives in the conv1-output domain
                        r0 = hok ? r0 : 0.f;
                        r1 = hok ? r1 : 0.f;
                    }
                    c1h[(ri - 2) * C1PW + t + 1] = __floats2half2_rn(r0, r1);
                }
                if (ri >= 1 && ri <= NC1)      // middle taps of c1 row (ri-1)
                    s[(ri - 1) % 3] = fma2(K3, X.p0, fma2(K4, X.p1, fma2(K5, X.p2, s[(ri - 1) % 3])));
                if (ri <= NC1 - 1)             // start c1 row ri
                    s[ri % 3] = fma2(K0, X.p0, fma2(K1, X.p1, fma2(K2, X.p2, B1)));
                X = Xn;
            }
        }
        __syncthreads();

        // ---- conv2 (scatter into acc[TR], weights pre-scaled by cof) ----
        {
            const u64 S0 = pk2(cof * w2[0], cof * w2[0]), S1 = pk2(cof * w2[1], cof * w2[1]);
            const u64 S2 = pk2(cof * w2[2], cof * w2[2]), S3 = pk2(cof * w2[3], cof * w2[3]);
            const u64 S4 = pk2(cof * w2[4], cof * w2[4]), S5 = pk2(cof * w2[5], cof * w2[5]);
            const u64 S6 = pk2(cof * w2[6], cof * w2[6]), S7 = pk2(cof * w2[7], cof * w2[7]);
            const u64 S8 = pk2(cof * w2[8], cof * w2[8]);

            __half2 A  = c1h[0 * C1PW + t];
            __half2 Bp = c1h[0 * C1PW + t + 1];
            __half2 Cp = c1h[0 * C1PW + t + 2];
#pragma unroll
            for (int rr = 0; rr < NC1; rr++) {
                __half2 An, Bn, Cn;
                if (rr + 1 < NC1) {
                    An = c1h[(rr + 1) * C1PW + t];
                    Bn = c1h[(rr + 1) * C1PW + t + 1];
                    Cn = c1h[(rr + 1) * C1PW + t + 2];
                }
                float fb = __high2float(A);    // col 2t-1
                float fc = __low2float(Bp);    // col 2t
                float fd = __high2float(Bp);   // col 2t+1
                float fe = __low2float(Cp);    // col 2t+2
                u64 p0 = pk2(fb, fc);
                u64 p1 = pk2(fc, fd);
                u64 p2 = pk2(fd, fe);
                if (rr <= TR - 1)
                    acc[rr]     = fma2(S0, p0, fma2(S1, p1, fma2(S2, p2, acc[rr])));
                if (rr >= 1 && rr <= TR)
                    acc[rr - 1] = fma2(S3, p0, fma2(S4, p1, fma2(S5, p2, acc[rr - 1])));
                if (rr >= 2)
                    acc[rr - 2] = fma2(S6, p0, fma2(S7, p1, fma2(S8, p2, acc[rr - 2])));
                A = An; Bp = Bn; Cp = Cn;
            }
        }
        __syncthreads();
    }
}

__global__ __launch_bounds__(96) void moe_kernel(
    const float* __restrict__ x,
    const float* __restrict__ ew1, const float* __restrict__ eb1,
    const float* __restrict__ ew2, const float* __restrict__ eb2,
    float* __restrict__ out)
{
    const int t  = threadIdx.x;             // 0..95, column pair (2t, 2t+1)
    const int h0 = blockIdx.x * TR;
    const int c  = blockIdx.y;
    const int b  = blockIdx.z;
    const bool vedge = (blockIdx.x == 0) || (blockIdx.x == (HH / TR - 1));

    // x tile: rows h0-2..h0+TR+1 (NIN), col j at idx j+1; idx 0 & 193 zero pad
    __shared__ __align__(16) float in_s[NIN * INW];
    // relu(conv1) as fp16x2 pairs: rows h0-1..h0+TR (NC1)
    __shared__ __half2 c1h[NC1 * C1PW];

    // ---- vectorized tile load: NIN row passes, 1 coalesced float2 each ----
    const float* xp = x + (size_t)(b * DIM + c) * (HH * WW);
#pragma unroll 4
    for (int ri = 0; ri < NIN; ri++) {
        const int h = h0 - 2 + ri;
        float2 v = make_float2(0.f, 0.f);
        if ((unsigned)h < (unsigned)HH)
            v = reinterpret_cast<const float2*>(xp + h * WW)[t];
        in_s[ri * INW + 2 * t + 1] = v.x;
        in_s[ri * INW + 2 * t + 2] = v.y;
        if (t == 0) { in_s[ri * INW + 0] = 0.f; in_s[ri * INW + 193] = 0.f; }
    }
    // c1 halo pairs: idx 0 = cols(-2,-1), idx 97 = cols(192,193): always zero
    if (t < NC1) {
        c1h[t * C1PW + 0]  = __floats2half2_rn(0.f, 0.f);
        c1h[t * C1PW + 97] = __floats2half2_rn(0.f, 0.f);
    }

    // acc init = sum of all selected experts' conv2 biases (data-independent)
    float bsum = 0.f;
#pragma unroll
    for (int ki = 0; ki < TOPK; ki++)
        bsum += g_w[b * TOPK + ki] * eb2[g_idx[b * TOPK + ki] * DIM + c];
    u64 acc[TR];
    const u64 BINIT = pk2(bsum, bsum);
#pragma unroll
    for (int r = 0; r < TR; r++) acc[r] = BINIT;
    __syncthreads();

    const float2* in2 = reinterpret_cast<const float2*>(in_s);
    if (vedge)
        run_experts<true >(in2, c1h, acc, t, h0, b, c, ew1, eb1, ew2, eb2);
    else
        run_experts<false>(in2, c1h, acc, t, h0, b, c, ew1, eb1, ew2, eb2);

    float* op = out + (size_t)(b * DIM + c) * (HH * WW) + h0 * WW + 2 * t;
#pragma unroll
    for (int r = 0; r < TR; r++) {
        float o0, o1; upk2(acc[r], o0, o1);
        reinterpret_cast<float2*>(op + r * WW)[0] = make_float2(o0, o1);
    }
}

// ---------------------------------------------------------------
extern "C" void kernel_launch(void* const* d_in, const int* in_sizes, int n_in,
                              void* d_out, int out_size) {
    const float* x     = (const float*)d_in[0];
    const float* w_fc0 = (const float*)d_in[1];
    const float* b_fc0 = (const float*)d_in[2];
    const float* w_fc1 = (const float*)d_in[3];
    const float* b_fc1 = (const float*)d_in[4];
    const float* ew1   = (const float*)d_in[5];
    const float* eb1   = (const float*)d_in[6];
    const float* ew2   = (const float*)d_in[7];
    const float* eb2   = (const float*)d_in[8];
    float* out = (float*)d_out;

    pool_gate_kernel<<<BATCH * DIM, 256>>>(x, w_fc0, b_fc0, w_fc1, b_fc1);
    dim3 grid(HH / TR, DIM, BATCH);
    moe_kernel<<<grid, 96>>>(x, ew1, eb1, ew2, eb2, out);
}

// round 16
// speedup vs baseline: 1.0475x; 1.0475x over previous
#include <cuda_runtime.h>
#include <cuda_bf16.h>
#include <cuda_fp16.h>
#include <math.h>

#define BATCH 8
#define DIM 96
#define HH 192
#define WW 192
#define NEXP 6
#define TOPK 3

#define TR 12             // output rows per tile
#define NIN (TR + 4)      // input rows per tile (16)
#define NC1 (TR + 2)      // conv1 rows per tile (14)

typedef unsigned long long u64;

// ---------- packed f32x2 helpers (sm_103a) ----------
__device__ __forceinline__ u64 pk2(float lo, float hi) {
    u64 d; asm("mov.b64 %0, {%1, %2};" : "=l"(d) : "f"(lo), "f"(hi)); return d;
}
__device__ __forceinline__ void upk2(u64 d, float& lo, float& hi) {
    asm("mov.b64 {%0, %1}, %2;" : "=f"(lo), "=f"(hi) : "l"(d));
}
__device__ __forceinline__ u64 fma2(u64 a, u64 b, u64 c) {
    u64 d; asm("fma.rn.f32x2 %0, %1, %2, %3;" : "=l"(d) : "l"(a), "l"(b), "l"(c)); return d;
}

// ---------- device scratch ----------
__device__ float g_pooled[BATCH * DIM];
__device__ int   g_idx[BATCH * TOPK];
__device__ float g_w[BATCH * TOPK];
__device__ unsigned int g_done = 0;   // self-resetting completion counter

// ---------------------------------------------------------------
// Kernel A: fused pooling + gate (last-block pattern, self-resetting).
// ---------------------------------------------------------------
__global__ __launch_bounds__(256) void pool_gate_kernel(
    const float* __restrict__ x,
    const float* __restrict__ w_fc0, const float* __restrict__ b_fc0,
    const float* __restrict__ w_fc1, const float* __restrict__ b_fc1)
{
    __shared__ float smx[8], ssm[8];
    __shared__ int   s_last;
    __shared__ float sh_g[BATCH][NEXP], sh_nz[BATCH][NEXP];

    const int bc = blockIdx.x;
    const int tid = threadIdx.x;
    const float4* p4 = reinterpret_cast<const float4*>(x + (size_t)bc * (HH * WW));
    float mx = -1e30f, sm = 0.f;
    for (int i = tid; i < (HH * WW / 4); i += 256) {
        float4 v = p4[i];
        mx = fmaxf(mx, fmaxf(fmaxf(v.x, v.y), fmaxf(v.z, v.w)));
        sm += (v.x + v.y) + (v.z + v.w);
    }
#pragma unroll
    for (int o = 16; o; o >>= 1) {
        mx = fmaxf(mx, __shfl_xor_sync(0xffffffffu, mx, o));
        sm += __shfl_xor_sync(0xffffffffu, sm, o);
    }
    int w = tid >> 5, l = tid & 31;
    if (l == 0) { smx[w] = mx; ssm[w] = sm; }
    __syncthreads();
    if (tid == 0) {
        float M = smx[0], S = ssm[0];
#pragma unroll
        for (int i = 1; i < 8; i++) { M = fmaxf(M, smx[i]); S += ssm[i]; }
        g_pooled[bc] = M + S * (1.0f / (HH * WW));
        __threadfence();                                   // release g_pooled
        unsigned int old = atomicAdd(&g_done, 1u);
        s_last = (old == (unsigned)(BATCH * DIM - 1)) ? 1 : 0;
    }
    __syncthreads();
    if (!s_last) return;

    // ---- last block: gate ----
    __threadfence();                                       // acquire g_pooled
    if (tid == 0) g_done = 0;                              // reset for replay
    if (tid < BATCH * NEXP) {
        int b = tid / NEXP, e = tid - b * NEXP;
        const float* p = g_pooled + b * DIM;
        float d0 = b_fc0[e], d1 = b_fc1[e];
        for (int c = 0; c < DIM; c++) {
            float pv = p[c];
            d0 = fmaf(pv, w_fc0[e * DIM + c], d0);
            d1 = fmaf(pv, w_fc1[e * DIM + c], d1);
        }
        sh_g[b][e]  = (d1 >= 0.f) ? d1 : 0.2f * d1;                  // leaky_relu 0.2
        sh_nz[b][e] = fmaxf(d0, 0.f) + log1pf(expf(-fabsf(d0)));     // stable softplus
    }
    __syncthreads();
    if (tid < BATCH) {
        int b = tid;
        float g[NEXP], nz[NEXP];
#pragma unroll
        for (int e = 0; e < NEXP; e++) { g[e] = sh_g[b][e]; nz[e] = sh_nz[b][e]; }
        float mu = 0.f;
#pragma unroll
        for (int e = 0; e < NEXP; e++) mu += nz[e];
        mu *= (1.0f / NEXP);
        float var = 0.f;
#pragma unroll
        for (int e = 0; e < NEXP; e++) { float d = nz[e] - mu; var += d * d; }
        float sd = sqrtf(var / (NEXP - 1));                          // ddof=1
        float sc[NEXP];
#pragma unroll
        for (int e = 0; e < NEXP; e++) sc[e] = g[e] + (nz[e] - mu) / sd;

        bool used[NEXP] = {false, false, false, false, false, false};
        int idx[TOPK];
#pragma unroll
        for (int k = 0; k < TOPK; k++) {
            float best = -1e30f; int bi = 0;
#pragma unroll
            for (int e = 0; e < NEXP; e++)
                if (!used[e] && sc[e] > best) { best = sc[e]; bi = e; }
            used[bi] = true;
            idx[k] = bi;
        }
        float m = fmaxf(g[idx[0]], fmaxf(g[idx[1]], g[idx[2]]));
        float ex[TOPK], s = 0.f;
#pragma unroll
        for (int k = 0; k < TOPK; k++) { ex[k] = expf(g[idx[k]] - m); s += ex[k]; }
        float inv = 1.0f / s;
#pragma unroll
        for (int k = 0; k < TOPK; k++) {
            g_idx[b * TOPK + k] = idx[k];
            g_w[b * TOPK + k]   = ex[k] * inv;
        }
    }
}

// ---------------------------------------------------------------
// Kernel C: fused conv1 -> relu -> conv2 -> weighted sum (f32x2).
// Exactly the R14 best kernel (12-row tiles, fp16x2 c1, scatter form,
// EDGE template) + conv2 biases hoisted into acc initialization.
// ---------------------------------------------------------------
#define INW 196
#define INW2 98
#define C1PW 100   // u32 pairs per c1 row

struct P3 { u64 p0, p1, p2; };

__device__ __forceinline__ P3 load3(const float2* row, int t) {
    float2 L = row[t];       // cols (2t-1, 2t)
    float2 R = row[t + 1];   // cols (2t+1, 2t+2)
    P3 r;
    r.p0 = pk2(L.x, L.y);
    r.p1 = pk2(L.y, R.x);
    r.p2 = pk2(R.x, R.y);
    return r;
}

template <bool EDGE>
__device__ __forceinline__ void run_experts(
    const float2* in2, __half2* c1h, u64* acc, int t, int h0, int b, int c,
    const float* __restrict__ ew1, const float* __restrict__ eb1,
    const float* __restrict__ ew2)
{
    for (int ki = 0; ki < TOPK; ki++) {
        const int   e   = g_idx[b * TOPK + ki];
        const float cof = g_w[b * TOPK + ki];
        const float* w1 = ew1 + ((size_t)e * DIM + c) * 9;
        const float* w2 = ew2 + ((size_t)e * DIM + c) * 9;

        // ---- conv1 + relu -> c1h (scatter, 3-slot circular accumulator) ----
        {
            const u64 K0 = pk2(w1[0], w1[0]), K1 = pk2(w1[1], w1[1]), K2 = pk2(w1[2], w1[2]);
            const u64 K3 = pk2(w1[3], w1[3]), K4 = pk2(w1[4], w1[4]), K5 = pk2(w1[5], w1[5]);
            const u64 K6 = pk2(w1[6], w1[6]), K7 = pk2(w1[7], w1[7]), K8 = pk2(w1[8], w1[8]);
            const float b1v = eb1[e * DIM + c];
            const u64 B1 = pk2(b1v, b1v);

            u64 s[3];
#pragma unroll
            for (int ri = 0; ri < NIN; ri++) {
                P3 X = load3(in2 + ri * INW2, t);
                if (ri >= 2) {          // finish c1 row (ri-2), store as fp16x2
                    u64 v = fma2(K6, X.p0, fma2(K7, X.p1, fma2(K8, X.p2, s[(ri - 2) % 3])));
                    float v0, v1; upk2(v, v0, v1);
                    float r0 = fmaxf(v0, 0.f), r1 = fmaxf(v1, 0.f);
                    if (EDGE) {
                        const int hr = h0 + (ri - 2) - 1;
                        const bool hok = (unsigned)hr < (unsigned)HH;
                        // conv2's zero padding lives in the conv1-output domain
                        r0 = hok ? r0 : 0.f;
                        r1 = hok ? r1 : 0.f;
                    }
                    c1h[(ri - 2) * C1PW + t + 1] = __floats2half2_rn(r0, r1);
                }
                if (ri >= 1 && ri <= NC1)      // middle taps of c1 row (ri-1)
                    s[(ri - 1) % 3] = fma2(K3, X.p0, fma2(K4, X.p1, fma2(K5, X.p2, s[(ri - 1) % 3])));
                if (ri <= NC1 - 1)             // start c1 row ri
                    s[ri % 3] = fma2(K0, X.p0, fma2(K1, X.p1, fma2(K2, X.p2, B1)));
            }
        }
        __syncthreads();

        // ---- conv2 (scatter into acc[TR], weights pre-scaled by cof) ----
        {
            const u64 S0 = pk2(cof * w2[0], cof * w2[0]), S1 = pk2(cof * w2[1], cof * w2[1]);
            const u64 S2 = pk2(cof * w2[2], cof * w2[2]), S3 = pk2(cof * w2[3], cof * w2[3]);
            const u64 S4 = pk2(cof * w2[4], cof * w2[4]), S5 = pk2(cof * w2[5], cof * w2[5]);
            const u64 S6 = pk2(cof * w2[6], cof * w2[6]), S7 = pk2(cof * w2[7], cof * w2[7]);
            const u64 S8 = pk2(cof * w2[8], cof * w2[8]);

#pragma unroll
            for (int rr = 0; rr < NC1; rr++) {
                __half2 A  = c1h[rr * C1PW + t];
                __half2 Bp = c1h[rr * C1PW + t + 1];
                __half2 Cp = c1h[rr * C1PW + t + 2];
                float fb = __high2float(A);    // col 2t-1
                float fc = __low2float(Bp);    // col 2t
                float fd = __high2float(Bp);   // col 2t+1
                float fe = __low2float(Cp);    // col 2t+2
                u64 p0 = pk2(fb, fc);
                u64 p1 = pk2(fc, fd);
                u64 p2 = pk2(fd, fe);
                if (rr <= TR - 1)
                    acc[rr]     = fma2(S0, p0, fma2(S1, p1, fma2(S2, p2, acc[rr])));
                if (rr >= 1 && rr <= TR)
                    acc[rr - 1] = fma2(S3, p0, fma2(S4, p1, fma2(S5, p2, acc[rr - 1])));
                if (rr >= 2)
                    acc[rr - 2] = fma2(S6, p0, fma2(S7, p1, fma2(S8, p2, acc[rr - 2])));
            }
        }
        __syncthreads();
    }
}

__global__ __launch_bounds__(96) void moe_kernel(
    const float* __restrict__ x,
    const float* __restrict__ ew1, const float* __restrict__ eb1,
    const float* __restrict__ ew2, const float* __restrict__ eb2,
    float* __restrict__ out)
{
    const int t  = threadIdx.x;             // 0..95, column pair (2t, 2t+1)
    const int h0 = blockIdx.x * TR;
    const int c  = blockIdx.y;
    const int b  = blockIdx.z;
    const bool vedge = (blockIdx.x == 0) || (blockIdx.x == (HH / TR - 1));

    // x tile: rows h0-2..h0+TR+1 (NIN), col j at idx j+1; idx 0 & 193 zero pad
    __shared__ __align__(16) float in_s[NIN * INW];
    // relu(conv1) as fp16x2 pairs: rows h0-1..h0+TR (NC1)
    __shared__ __half2 c1h[NC1 * C1PW];

    // ---- vectorized tile load: NIN row passes, 1 coalesced float2 each ----
    const float* xp = x + (size_t)(b * DIM + c) * (HH * WW);
#pragma unroll 4
    for (int ri = 0; ri < NIN; ri++) {
        const int h = h0 - 2 + ri;
        float2 v = make_float2(0.f, 0.f);
        if ((unsigned)h < (unsigned)HH)
            v = reinterpret_cast<const float2*>(xp + h * WW)[t];
        in_s[ri * INW + 2 * t + 1] = v.x;
        in_s[ri * INW + 2 * t + 2] = v.y;
        if (t == 0) { in_s[ri * INW + 0] = 0.f; in_s[ri * INW + 193] = 0.f; }
    }
    // c1 halo pairs: idx 0 = cols(-2,-1), idx 97 = cols(192,193): always zero
    if (t < NC1) {
        c1h[t * C1PW + 0]  = __floats2half2_rn(0.f, 0.f);
        c1h[t * C1PW + 97] = __floats2half2_rn(0.f, 0.f);
    }

    // acc init = sum of the selected experts' conv2 biases (data-independent)
    float bsum = 0.f;
#pragma unroll
    for (int ki = 0; ki < TOPK; ki++)
        bsum += g_w[b * TOPK + ki] * eb2[g_idx[b * TOPK + ki] * DIM + c];
    u64 acc[TR];
    const u64 BINIT = pk2(bsum, bsum);
#pragma unroll
    for (int r = 0; r < TR; r++) acc[r] = BINIT;
    __syncthreads();

    const float2* in2 = reinterpret_cast<const float2*>(in_s);
    if (vedge)
        run_experts<true >(in2, c1h, acc, t, h0, b, c, ew1, eb1, ew2);
    else
        run_experts<false>(in2, c1h, acc, t, h0, b, c, ew1, eb1, ew2);

    float* op = out + (size_t)(b * DIM + c) * (HH * WW) + h0 * WW + 2 * t;
#pragma unroll
    for (int r = 0; r < TR; r++) {
        float o0, o1; upk2(acc[r], o0, o1);
        reinterpret_cast<float2*>(op + r * WW)[0] = make_float2(o0, o1);
    }
}

// ---------------------------------------------------------------
extern "C" void kernel_launch(void* const* d_in, const int* in_sizes, int n_in,
                              void* d_out, int out_size) {
    const float* x     = (const float*)d_in[0];
    const float* w_fc0 = (const float*)d_in[1];
    const float* b_fc0 = (const float*)d_in[2];
    const float* w_fc1 = (const float*)d_in[3];
    const float* b_fc1 = (const float*)d_in[4];
    const float* ew1   = (const float*)d_in[5];
    const float* eb1   = (const float*)d_in[6];
    const float* ew2   = (const float*)d_in[7];
    const float* eb2   = (const float*)d_in[8];
    float* out = (float*)d_out;

    pool_gate_kernel<<<BATCH * DIM, 256>>>(x, w_fc0, b_fc0, w_fc1, b_fc1);
    dim3 grid(HH / TR, DIM, BATCH);
    moe_kernel<<<grid, 96>>>(x, ew1, eb1, ew2, eb2, out);
}